// round 1
// baseline (speedup 1.0000x reference)
#include <cuda_runtime.h>
#include <cstdint>

// Problem constants
#define B_  256
#define L_  500
#define E_  300
#define H_  10
#define K_  5

#define NT      256          // threads per block
#define EC      15           // e-columns per staging chunk
#define NCHUNK  20           // 300 / 15
#define RSROW   17           // EC + 2 pad, gcd(17,32)=1 -> conflict-free strided LDS
#define RSBUF   (L_ * RSROW) // 8500 floats per staging buffer
#define NPAIR   25           // (K_*H_)/2 packed output pairs

// shared-memory layout (float offsets)
#define OFF_WP    0                    // 7500 float2 = 15000 floats (packed weights)
#define OFF_PROJ  15000                // 50*500 = 25000 floats  proj[kh][l]
#define OFF_AE    40000                // 150 floats (aspEmbed)
#define OFF_RS    40152                // 2*8500 = 17000 floats (staging; aliased as scores)
#define SMEM_FLOATS (OFF_RS + 2 * RSBUF)   // 57152
#define SMEM_BYTES  (SMEM_FLOATS * 4)      // 228608 <= 232448

typedef unsigned long long ull;

__device__ __forceinline__ ull ffma2(ull a, ull b, ull c) {
    ull d;
    asm("fma.rn.f32x2 %0, %1, %2, %3;" : "=l"(d) : "l"(a), "l"(b), "l"(c));
    return d;
}
__device__ __forceinline__ ull pack2(float lo, float hi) {
    ull r;
    asm("mov.b64 %0, {%1, %2};" : "=l"(r) : "f"(lo), "f"(hi));
    return r;
}
__device__ __forceinline__ float2 unpack2(ull v) {
    float2 f;
    asm("mov.b64 {%0, %1}, %2;" : "=f"(f.x), "=f"(f.y) : "l"(v));
    return f;
}

__global__ __launch_bounds__(NT, 1)
void anr_arl_kernel(const float* __restrict__ review,
                    const float* __restrict__ aspProj,
                    const float* __restrict__ aspEmbed,
                    float* __restrict__ out)
{
    extern __shared__ float sm[];
    float2* sWp    = reinterpret_cast<float2*>(sm + OFF_WP);   // [e*25 + p]
    float*  sProj  = sm + OFF_PROJ;                            // [kh*500 + l]
    float*  sAE    = sm + OFF_AE;                              // [k*30 + h*3 + i]
    float*  sRS    = sm + OFF_RS;                              // staging (double buffer)
    float*  sScores = sRS;                                     // alias (2500 floats), used post-GEMM

    const int tid = threadIdx.x;
    const int b   = blockIdx.x;
    const float* revB = review + (size_t)b * (L_ * E_);
    const unsigned rs_u32 = (unsigned)__cvta_generic_to_shared(sRS);

    // ---- prologue: stage packed weights + aspEmbed into smem ----
    // Wp[e][p] = (aspProj[k,e,h0], aspProj[k,e,h0+1]) with kh0 = 2p (never crosses k: H even)
    for (int idx = tid; idx < E_ * NPAIR; idx += NT) {
        int e = idx / NPAIR, p = idx - e * NPAIR;
        int kh = 2 * p;
        int k = kh / H_, h = kh - k * H_;
        sWp[idx] = *reinterpret_cast<const float2*>(aspProj + (k * E_ + e) * H_ + h);
    }
    for (int idx = tid; idx < K_ * 3 * H_; idx += NT) sAE[idx] = aspEmbed[idx];

    // ---- cp.async staging of review e-column chunks ----
    auto stage = [&](int c) {
        const int e0 = c * EC;
        const unsigned dbase = rs_u32 + (((unsigned)(c & 1) * RSBUF) << 2);
        const float* src0 = revB + e0;
        for (int idx = tid; idx < L_ * EC; idx += NT) {
            int l = idx / EC, j = idx - l * EC;
            unsigned d = dbase + ((unsigned)(l * RSROW + j) << 2);
            const float* s = src0 + l * E_ + j;
            asm volatile("cp.async.ca.shared.global [%0], [%1], 4;" :: "r"(d), "l"(s) : "memory");
        }
        asm volatile("cp.async.commit_group;" ::: "memory");
    };

    // accumulators: 2 l-rows x 25 kh-pairs, packed f32x2
    ull acc0[NPAIR], acc1[NPAIR];
#pragma unroll
    for (int p = 0; p < NPAIR; p++) { acc0[p] = 0ull; acc1[p] = 0ull; }

    const int l0 = tid;                 // always < 500
    const int l1 = tid + NT;            // 256..511
    const int lr1 = (l1 < L_) ? l1 : 0; // clamp reads; stores skipped when OOB

    stage(0);

    const ull* WqAll = reinterpret_cast<const ull*>(sWp);

    for (int c = 0; c < NCHUNK; c++) {
        if (c + 1 < NCHUNK) {
            stage(c + 1);
            asm volatile("cp.async.wait_group 1;" ::: "memory");
        } else {
            asm volatile("cp.async.wait_group 0;" ::: "memory");
        }
        __syncthreads();

        const float* rb = sRS + (c & 1) * RSBUF;
        const ull* Wq = WqAll + c * EC * NPAIR;

#pragma unroll 3
        for (int j = 0; j < EC; j++) {
            float a0 = rb[l0 * RSROW + j];
            float a1 = rb[lr1 * RSROW + j];
            ull a0p = pack2(a0, a0);
            ull a1p = pack2(a1, a1);
            const ull* w = Wq + j * NPAIR;
#pragma unroll
            for (int p = 0; p < NPAIR; p++) {
                acc0[p] = ffma2(a0p, w[p], acc0[p]);
                acc1[p] = ffma2(a1p, w[p], acc1[p]);
            }
        }
        __syncthreads();   // before next chunk's cp.async overwrites this buffer
    }

    // ---- write proj tile to smem: proj[kh][l] ----
#pragma unroll
    for (int p = 0; p < NPAIR; p++) {
        float2 v = unpack2(acc0[p]);
        sProj[(2 * p) * L_ + l0]     = v.x;
        sProj[(2 * p + 1) * L_ + l0] = v.y;
    }
    if (l1 < L_) {
#pragma unroll
        for (int p = 0; p < NPAIR; p++) {
            float2 v = unpack2(acc1[p]);
            sProj[(2 * p) * L_ + l1]     = v.x;
            sProj[(2 * p + 1) * L_ + l1] = v.y;
        }
    }
    __syncthreads();

    // ---- window-3 attention scores: scores[k][l] ----
    // scores = sum_h sum_{i=0..2} proj[k, l-1+i, h] * aspEmbed[k, h*3+i], zero-padded seq
    for (int idx = tid; idx < K_ * L_; idx += NT) {
        int k = idx / L_, l = idx - k * L_;
        const float* aEk = sAE + k * 3 * H_;
        const float* pk  = sProj + k * H_ * L_;
        float s = 0.f;
#pragma unroll
        for (int i = 0; i < 3; i++) {
            int ll = l - 1 + i;
            if ((unsigned)ll < (unsigned)L_) {
#pragma unroll
                for (int h = 0; h < H_; h++)
                    s += pk[h * L_ + ll] * aEk[h * 3 + i];
            }
        }
        sScores[idx] = s;
    }
    __syncthreads();

    // ---- softmax over l per k (warp k handles row k), write attn out ----
    const int warp = tid >> 5, lane = tid & 31;
    if (warp < K_) {
        float* srow = sScores + warp * L_;
        float m = -3.402823466e38f;
        for (int l = lane; l < L_; l += 32) m = fmaxf(m, srow[l]);
#pragma unroll
        for (int o = 16; o > 0; o >>= 1) m = fmaxf(m, __shfl_xor_sync(0xffffffffu, m, o));
        float ssum = 0.f;
        for (int l = lane; l < L_; l += 32) {
            float ev = expf(srow[l] - m);
            srow[l] = ev;
            ssum += ev;
        }
#pragma unroll
        for (int o = 16; o > 0; o >>= 1) ssum += __shfl_xor_sync(0xffffffffu, ssum, o);
        float inv = 1.0f / ssum;
        float* oa = out + (size_t)b * (K_ * L_) + warp * L_;   // (B,K,L)
        for (int l = lane; l < L_; l += 32) {
            float a = srow[l] * inv;
            srow[l] = a;          // keep normalized attn in smem for pooling
            oa[l] = a;
        }
    }
    __syncthreads();

    // ---- pooled rep: rep[k][h] = sum_l proj[kh][l] * attn[k][l] ----
    float* orep = out + (size_t)B_ * K_ * L_ + (size_t)b * (K_ * H_);   // (B,K,H)
    for (int kh = warp; kh < K_ * H_; kh += (NT / 32)) {
        int k = kh / H_;
        const float* pk = sProj + kh * L_;
        const float* ak = sScores + k * L_;
        float s = 0.f;
        for (int l = lane; l < L_; l += 32) s += pk[l] * ak[l];
#pragma unroll
        for (int o = 16; o > 0; o >>= 1) s += __shfl_xor_sync(0xffffffffu, s, o);
        if (lane == 0) orep[kh] = s;
    }
}

extern "C" void kernel_launch(void* const* d_in, const int* in_sizes, int n_in,
                              void* d_out, int out_size)
{
    const float* review   = (const float*)d_in[0];
    const float* aspProj  = (const float*)d_in[1];
    const float* aspEmbed = (const float*)d_in[2];
    float* out = (float*)d_out;

    cudaFuncSetAttribute(anr_arl_kernel,
                         cudaFuncAttributeMaxDynamicSharedMemorySize, SMEM_BYTES);
    anr_arl_kernel<<<B_, NT, SMEM_BYTES>>>(review, aspProj, aspEmbed, out);
}

// round 2
// speedup vs baseline: 1.0980x; 1.0980x over previous
#include <cuda_runtime.h>
#include <cstdint>

// Problem constants
#define B_  256
#define L_  500
#define E_  300
#define H_  10
#define K_  5

#define NT      512          // threads per block (1 l-row per thread)
#define NPAIR   25           // (K_*H_)/2 packed kh pairs
#define WSTRIDE 26           // padded pairs per e (16B alignment for LDS.128)

// shared-memory layout (float offsets)
#define OFF_WP     0                         // 300*26 ull = 15600 floats (padded packed weights)
#define OFF_PROJ   15600                     // 50*500 = 25000 floats  proj[kh][l]
#define OFF_AE     40600                     // 150 floats (aspEmbed), pad to 152
#define OFF_SC     40752                     // 2500 floats (scores/attn)
#define SMEM_FLOATS (OFF_SC + K_ * L_)       // 43252
#define SMEM_BYTES  (SMEM_FLOATS * 4)        // 173008 B

typedef unsigned long long ull;

__device__ __forceinline__ ull ffma2(ull a, ull b, ull c) {
    ull d;
    asm("fma.rn.f32x2 %0, %1, %2, %3;" : "=l"(d) : "l"(a), "l"(b), "l"(c));
    return d;
}
__device__ __forceinline__ ull pack2(float lo, float hi) {
    ull r;
    asm("mov.b64 %0, {%1, %2};" : "=l"(r) : "f"(lo), "f"(hi));
    return r;
}
__device__ __forceinline__ float2 unpack2(ull v) {
    float2 f;
    asm("mov.b64 {%0, %1}, %2;" : "=f"(f.x), "=f"(f.y) : "l"(v));
    return f;
}

__global__ __launch_bounds__(NT, 1)
void anr_arl_kernel(const float* __restrict__ review,
                    const float* __restrict__ aspProj,
                    const float* __restrict__ aspEmbed,
                    float* __restrict__ out)
{
    extern __shared__ float sm[];
    ull*   sWp     = reinterpret_cast<ull*>(sm + OFF_WP);   // [e*26 + p], p<25 valid, p=25 zero pad
    float* sProj   = sm + OFF_PROJ;                          // [kh*500 + l]
    float* sAE     = sm + OFF_AE;                            // [k*30 + h*3 + i]
    float* sScores = sm + OFF_SC;                            // [k*500 + l]

    const int tid = threadIdx.x;
    const int b   = blockIdx.x;
    const float* revB = review + (size_t)b * (L_ * E_);

    // ---- prologue: packed+padded weights and aspEmbed into smem ----
    // Wp[e][p] = (aspProj[k,e,2p%H], aspProj[k,e,2p%H+1]); kh pairs never cross k (H even)
    for (int idx = tid; idx < E_ * WSTRIDE; idx += NT) {
        int e = idx / WSTRIDE, p = idx - e * WSTRIDE;
        ull v = 0ull;
        if (p < NPAIR) {
            int kh = 2 * p;
            int k = kh / H_, h = kh - k * H_;
            float2 w = *reinterpret_cast<const float2*>(aspProj + (k * E_ + e) * H_ + h);
            v = pack2(w.x, w.y);
        }
        sWp[idx] = v;
    }
    for (int idx = tid; idx < K_ * 3 * H_; idx += NT) sAE[idx] = aspEmbed[idx];
    __syncthreads();

    // ---- GEMM: each thread computes proj[:, l] for its own row l ----
    const bool active = (tid < L_);
    const int  lr     = active ? tid : 0;           // inactive threads read row 0, discard
    const float4* rp  = reinterpret_cast<const float4*>(revB + (size_t)lr * E_);
    const ulonglong2* W2 = reinterpret_cast<const ulonglong2*>(sWp);

    ull acc[NPAIR + 1];
#pragma unroll
    for (int p = 0; p <= NPAIR; p++) acc[p] = 0ull;

#pragma unroll 2
    for (int eo = 0; eo < E_ / 4; eo++) {
        float4 a = __ldg(rp + eo);
#pragma unroll
        for (int i = 0; i < 4; i++) {
            float av = (i == 0) ? a.x : (i == 1) ? a.y : (i == 2) ? a.z : a.w;
            ull ap = pack2(av, av);
            const ulonglong2* w = W2 + (eo * 4 + i) * (WSTRIDE / 2);
#pragma unroll
            for (int q = 0; q < WSTRIDE / 2; q++) {
                ulonglong2 wv = w[q];
                acc[2 * q]     = ffma2(ap, wv.x, acc[2 * q]);
                acc[2 * q + 1] = ffma2(ap, wv.y, acc[2 * q + 1]);  // q=12 hits zero pad -> harmless
            }
        }
    }

    // ---- write proj tile to smem: proj[kh][l] ----
    if (active) {
#pragma unroll
        for (int p = 0; p < NPAIR; p++) {
            float2 v = unpack2(acc[p]);
            sProj[(2 * p) * L_ + lr]     = v.x;
            sProj[(2 * p + 1) * L_ + lr] = v.y;
        }
    }
    __syncthreads();

    // ---- window-3 attention scores: scores[k][l] ----
    for (int idx = tid; idx < K_ * L_; idx += NT) {
        int k = idx / L_, l = idx - k * L_;
        const float* aEk = sAE + k * 3 * H_;
        const float* pk  = sProj + k * H_ * L_;
        float s = 0.f;
#pragma unroll
        for (int i = 0; i < 3; i++) {
            int ll = l - 1 + i;
            if ((unsigned)ll < (unsigned)L_) {
#pragma unroll
                for (int h = 0; h < H_; h++)
                    s += pk[h * L_ + ll] * aEk[h * 3 + i];
            }
        }
        sScores[idx] = s;
    }
    __syncthreads();

    // ---- softmax over l per k (warp k handles row k), write attn out ----
    const int warp = tid >> 5, lane = tid & 31;
    if (warp < K_) {
        float* srow = sScores + warp * L_;
        float m = -3.402823466e38f;
        for (int l = lane; l < L_; l += 32) m = fmaxf(m, srow[l]);
#pragma unroll
        for (int o = 16; o > 0; o >>= 1) m = fmaxf(m, __shfl_xor_sync(0xffffffffu, m, o));
        float ssum = 0.f;
        for (int l = lane; l < L_; l += 32) {
            float ev = expf(srow[l] - m);
            srow[l] = ev;
            ssum += ev;
        }
#pragma unroll
        for (int o = 16; o > 0; o >>= 1) ssum += __shfl_xor_sync(0xffffffffu, ssum, o);
        float inv = 1.0f / ssum;
        float* oa = out + (size_t)b * (K_ * L_) + warp * L_;   // (B,K,L)
        for (int l = lane; l < L_; l += 32) {
            float a = srow[l] * inv;
            srow[l] = a;          // keep normalized attn in smem for pooling
            oa[l] = a;
        }
    }
    __syncthreads();

    // ---- pooled rep: rep[k][h] = sum_l proj[kh][l] * attn[k][l] ----
    float* orep = out + (size_t)B_ * K_ * L_ + (size_t)b * (K_ * H_);   // (B,K,H)
    for (int kh = warp; kh < K_ * H_; kh += (NT / 32)) {
        int k = kh / H_;
        const float* pk = sProj + kh * L_;
        const float* ak = sScores + k * L_;
        float s = 0.f;
        for (int l = lane; l < L_; l += 32) s += pk[l] * ak[l];
#pragma unroll
        for (int o = 16; o > 0; o >>= 1) s += __shfl_xor_sync(0xffffffffu, s, o);
        if (lane == 0) orep[kh] = s;
    }
}

extern "C" void kernel_launch(void* const* d_in, const int* in_sizes, int n_in,
                              void* d_out, int out_size)
{
    const float* review   = (const float*)d_in[0];
    const float* aspProj  = (const float*)d_in[1];
    const float* aspEmbed = (const float*)d_in[2];
    float* out = (float*)d_out;

    cudaFuncSetAttribute(anr_arl_kernel,
                         cudaFuncAttributeMaxDynamicSharedMemorySize, SMEM_BYTES);
    anr_arl_kernel<<<B_, NT, SMEM_BYTES>>>(review, aspProj, aspEmbed, out);
}